// round 3
// baseline (speedup 1.0000x reference)
#include <cuda_runtime.h>
#include <cuda_bf16.h>

#define N_NODES 10000
#define N_EDGES 640000
#define F_IN    128
#define F_H     128
#define F_OUT   64

// ---------------- scratch (device globals; no allocation allowed) ----------------
__device__ int   g_is64;
__device__ int   g_src[N_EDGES];
__device__ int   g_dst[N_EDGES];
__device__ int   g_cnt_out[N_NODES];
__device__ int   g_cnt_in[N_NODES];
__device__ float g_rs_out[N_NODES];
__device__ float g_rs_in[N_NODES];
__device__ int   g_row_start[N_NODES + 1];
__device__ int   g_fill[N_NODES];
__device__ int   g_csr[N_EDGES];          // src indices grouped by dst
__device__ float g_T1[N_NODES * F_H];     // (rs_out * X) @ W1
__device__ float g_H [N_NODES * F_H];     // relu(...) * rs_out (pre-scaled for layer2)
__device__ float g_T2[N_NODES * F_OUT];   // H @ W2

// ---------------- dtype detection (int64 vs int32 indices) ----------------
__global__ void k_detect(const unsigned int* __restrict__ raw) {
    if (threadIdx.x == 0 && blockIdx.x == 0) {
        int is64 = 1;
        for (int i = 0; i < 64; i++)
            if (raw[2 * i + 1] != 0u) is64 = 0;
        g_is64 = is64;
    }
}

__global__ void k_convert(const void* __restrict__ sraw, const void* __restrict__ draw) {
    int e = blockIdx.x * blockDim.x + threadIdx.x;
    if (e >= N_EDGES) return;
    if (g_is64) {
        g_src[e] = (int)((const long long*)sraw)[e];
        g_dst[e] = (int)((const long long*)draw)[e];
    } else {
        g_src[e] = ((const int*)sraw)[e];
        g_dst[e] = ((const int*)draw)[e];
    }
}

// ---------------- degree histogram ----------------
__global__ void k_zero_counts() {
    int i = blockIdx.x * blockDim.x + threadIdx.x;
    if (i < N_NODES) { g_cnt_out[i] = 0; g_cnt_in[i] = 0; }
}

__global__ void k_degree() {
    int e = blockIdx.x * blockDim.x + threadIdx.x;
    if (e >= N_EDGES) return;
    atomicAdd(&g_cnt_out[g_src[e]], 1);
    atomicAdd(&g_cnt_in [g_dst[e]], 1);
}

// ---------------- single-block scan + rsqrt degrees ----------------
__global__ void k_scan() {
    __shared__ int part[1024];
    const int t = threadIdx.x;
    const int CH = 10;                      // 1024*10 >= 10000
    int base = t * CH;
    int s = 0;
    for (int c = 0; c < CH; c++) {
        int idx = base + c;
        if (idx < N_NODES) s += g_cnt_in[idx];
    }
    part[t] = s;
    __syncthreads();
    for (int off = 1; off < 1024; off <<= 1) {
        int v = (t >= off) ? part[t - off] : 0;
        __syncthreads();
        part[t] += v;
        __syncthreads();
    }
    int run = (t > 0) ? part[t - 1] : 0;
    for (int c = 0; c < CH; c++) {
        int idx = base + c;
        if (idx < N_NODES) {
            g_row_start[idx] = run;
            g_fill[idx]      = run;
            run += g_cnt_in[idx];
        }
    }
    if (t == 0) g_row_start[N_NODES] = N_EDGES;
    // rsqrt of clipped degrees
    for (int i = t; i < N_NODES; i += 1024) {
        float dout = (float)max(g_cnt_out[i], 1);
        float din  = (float)max(g_cnt_in [i], 1);
        g_rs_out[i] = rsqrtf(dout);
        g_rs_in [i] = rsqrtf(din);
    }
}

// ---------------- CSR scatter ----------------
__global__ void k_scatter() {
    int e = blockIdx.x * blockDim.x + threadIdx.x;
    if (e >= N_EDGES) return;
    int d = g_dst[e];
    int pos = atomicAdd(&g_fill[d], 1);
    g_csr[pos] = g_src[e];
}

// ---------------- GEMM1: T1 = (rs_out * X) @ W1   [10000x128 @ 128x128] ----------------
__global__ void k_gemm1(const float* __restrict__ X, const float* __restrict__ W1) {
    const int nb = blockIdx.x * 4;
    const int j  = threadIdx.x;             // 0..127
    __shared__ float xs[4][F_IN];
    #pragma unroll
    for (int r = 0; r < 4; r++) {
        int node = nb + r;
        xs[r][j] = (node < N_NODES) ? X[node * F_IN + j] * g_rs_out[node] : 0.f;
    }
    __syncthreads();
    float a0 = 0.f, a1 = 0.f, a2 = 0.f, a3 = 0.f;
    #pragma unroll 8
    for (int k = 0; k < F_IN; k++) {
        float w = W1[k * F_H + j];
        a0 = fmaf(xs[0][k], w, a0);
        a1 = fmaf(xs[1][k], w, a1);
        a2 = fmaf(xs[2][k], w, a2);
        a3 = fmaf(xs[3][k], w, a3);
    }
    if (nb + 0 < N_NODES) g_T1[(nb + 0) * F_H + j] = a0;
    if (nb + 1 < N_NODES) g_T1[(nb + 1) * F_H + j] = a1;
    if (nb + 2 < N_NODES) g_T1[(nb + 2) * F_H + j] = a2;
    if (nb + 3 < N_NODES) g_T1[(nb + 3) * F_H + j] = a3;
}

// ---------------- SpMM1 + epilogue: H = relu(rs_in*SpMM(T1)+b1) * rs_out ----------------
__global__ void k_spmm1(const float* __restrict__ b1) {
    const int i = blockIdx.x;
    const int j = threadIdx.x;              // 0..127
    const int s = g_row_start[i];
    const int e = g_row_start[i + 1];
    __shared__ int se[128];
    float a0 = 0.f, a1 = 0.f, a2 = 0.f, a3 = 0.f;
    for (int cs = s; cs < e; cs += 128) {
        int cnt = min(128, e - cs);
        __syncthreads();
        if (j < cnt) se[j] = g_csr[cs + j];
        __syncthreads();
        int p = 0;
        for (; p + 4 <= cnt; p += 4) {
            a0 += g_T1[se[p + 0] * F_H + j];
            a1 += g_T1[se[p + 1] * F_H + j];
            a2 += g_T1[se[p + 2] * F_H + j];
            a3 += g_T1[se[p + 3] * F_H + j];
        }
        for (; p < cnt; p++) a0 += g_T1[se[p] * F_H + j];
    }
    float acc = (a0 + a1) + (a2 + a3);
    float h = fmaxf(fmaf(acc, g_rs_in[i], b1[j]), 0.f);
    g_H[i * F_H + j] = h * g_rs_out[i];
}

// ---------------- GEMM2: T2 = H @ W2   [10000x128 @ 128x64] ----------------
__global__ void k_gemm2(const float* __restrict__ W2) {
    const int nb = blockIdx.x * 8;
    const int j  = threadIdx.x;             // 0..63
    __shared__ float xs[8][F_H];
    for (int t = j; t < 8 * F_H; t += 64) {
        int r = t >> 7, c = t & 127;
        int node = nb + r;
        xs[r][c] = (node < N_NODES) ? g_H[node * F_H + c] : 0.f;
    }
    __syncthreads();
    float acc[8];
    #pragma unroll
    for (int r = 0; r < 8; r++) acc[r] = 0.f;
    #pragma unroll 4
    for (int k = 0; k < F_H; k++) {
        float w = W2[k * F_OUT + j];
        #pragma unroll
        for (int r = 0; r < 8; r++) acc[r] = fmaf(xs[r][k], w, acc[r]);
    }
    #pragma unroll
    for (int r = 0; r < 8; r++) {
        int node = nb + r;
        if (node < N_NODES) g_T2[node * F_OUT + j] = acc[r];
    }
}

// ---------------- SpMM2 + epilogue into d_out ----------------
__global__ void k_spmm2(const float* __restrict__ b2, float* __restrict__ out) {
    const int i = blockIdx.x;
    const int j = threadIdx.x;              // 0..63
    const int s = g_row_start[i];
    const int e = g_row_start[i + 1];
    __shared__ int se[128];
    float a0 = 0.f, a1 = 0.f, a2 = 0.f, a3 = 0.f;
    for (int cs = s; cs < e; cs += 128) {
        int cnt = min(128, e - cs);
        __syncthreads();
        for (int t = j; t < cnt; t += 64) se[t] = g_csr[cs + t];
        __syncthreads();
        int p = 0;
        for (; p + 4 <= cnt; p += 4) {
            a0 += g_T2[se[p + 0] * F_OUT + j];
            a1 += g_T2[se[p + 1] * F_OUT + j];
            a2 += g_T2[se[p + 2] * F_OUT + j];
            a3 += g_T2[se[p + 3] * F_OUT + j];
        }
        for (; p < cnt; p++) a0 += g_T2[se[p] * F_OUT + j];
    }
    float acc = (a0 + a1) + (a2 + a3);
    out[i * F_OUT + j] = fmaf(acc, g_rs_in[i], b2[j]);
}

// ---------------- launch ----------------
extern "C" void kernel_launch(void* const* d_in, const int* in_sizes, int n_in,
                              void* d_out, int out_size) {
    const float* in_feat = (const float*)d_in[0];
    const void*  src     = d_in[1];
    const void*  dst     = d_in[2];
    const float* W1      = (const float*)d_in[3];
    const float* b1      = (const float*)d_in[4];
    const float* W2      = (const float*)d_in[5];
    const float* b2      = (const float*)d_in[6];
    float* out = (float*)d_out;

    const int EB = (N_EDGES + 255) / 256;
    const int NB = (N_NODES + 255) / 256;

    k_detect<<<1, 32>>>((const unsigned int*)src);
    k_convert<<<EB, 256>>>(src, dst);
    k_zero_counts<<<NB, 256>>>();
    k_degree<<<EB, 256>>>();
    k_scan<<<1, 1024>>>();
    k_scatter<<<EB, 256>>>();
    k_gemm1<<<(N_NODES + 3) / 4, 128>>>(in_feat, W1);
    k_spmm1<<<N_NODES, 128>>>(b1);
    k_gemm2<<<(N_NODES + 7) / 8, 64>>>(W2);
    k_spmm2<<<N_NODES, 64>>>(b2, out);
}

// round 5
// speedup vs baseline: 1.2145x; 1.2145x over previous
#include <cuda_runtime.h>
#include <cuda_bf16.h>

#define N_NODES 10000
#define N_EDGES 640000
#define F_IN    128
#define F_H     128
#define F_OUT   64

typedef unsigned long long ull;

// ---------------- scratch (device globals; no allocation allowed) ----------------
__device__ int   g_is64;
__device__ int   g_src[N_EDGES];
__device__ int   g_dst[N_EDGES];
__device__ int   g_rank[N_EDGES];
__device__ int   g_cnt_out[N_NODES];
__device__ int   g_cnt_in[N_NODES];
__device__ float g_rs_out[N_NODES];
__device__ float g_rs_in[N_NODES];
__device__ int   g_row_start[N_NODES + 1];
__device__ int   g_csr[N_EDGES];          // src indices grouped by dst
__device__ float g_T1[N_NODES * F_H];     // (rs_out * X) @ W1
__device__ float g_H [N_NODES * F_H];     // relu(...) * rs_out (pre-scaled for layer2)
__device__ float g_T2[N_NODES * F_OUT];   // H @ W2

// ---------------- packed f32x2 FMA helpers ----------------
__device__ __forceinline__ ull fma2(ull a, ull b, ull c) {
    ull d;
    asm("fma.rn.f32x2 %0, %1, %2, %3;" : "=l"(d) : "l"(a), "l"(b), "l"(c));
    return d;
}
__device__ __forceinline__ ull pack2(float lo, float hi) {
    ull d;
    asm("mov.b64 %0, {%1, %2};" : "=l"(d) : "f"(lo), "f"(hi));
    return d;
}
__device__ __forceinline__ void unpack2(ull v, float& lo, float& hi) {
    asm("mov.b64 {%0, %1}, %2;" : "=f"(lo), "=f"(hi) : "l"(v));
}

// ---------------- dtype detection (int64 vs int32 indices) ----------------
__global__ void k_detect(const unsigned int* __restrict__ raw) {
    if (threadIdx.x == 0 && blockIdx.x == 0) {
        int is64 = 1;
        for (int i = 0; i < 64; i++)
            if (raw[2 * i + 1] != 0u) is64 = 0;
        g_is64 = is64;
    }
}

__global__ void k_zero() {
    int i = blockIdx.x * blockDim.x + threadIdx.x;
    if (i < N_NODES) { g_cnt_out[i] = 0; g_cnt_in[i] = 0; }
}

// ---------------- fused convert + degree + rank capture ----------------
__global__ void k_prep(const void* __restrict__ sraw, const void* __restrict__ draw) {
    int e = blockIdx.x * blockDim.x + threadIdx.x;
    if (e >= N_EDGES) return;
    int s, d;
    if (g_is64) {
        s = (int)((const long long*)sraw)[e];
        d = (int)((const long long*)draw)[e];
    } else {
        s = ((const int*)sraw)[e];
        d = ((const int*)draw)[e];
    }
    g_src[e] = s;
    g_dst[e] = d;
    atomicAdd(&g_cnt_out[s], 1);                 // RED (no return)
    g_rank[e] = atomicAdd(&g_cnt_in[d], 1);      // rank within CSR row
}

// ---------------- single-block scan + rsqrt degrees ----------------
__global__ void k_scan() {
    __shared__ int part[1024];
    const int t = threadIdx.x;
    const int CH = 10;
    int base = t * CH;
    int s = 0;
    for (int c = 0; c < CH; c++) {
        int idx = base + c;
        if (idx < N_NODES) s += g_cnt_in[idx];
    }
    part[t] = s;
    __syncthreads();
    for (int off = 1; off < 1024; off <<= 1) {
        int v = (t >= off) ? part[t - off] : 0;
        __syncthreads();
        part[t] += v;
        __syncthreads();
    }
    int run = (t > 0) ? part[t - 1] : 0;
    for (int c = 0; c < CH; c++) {
        int idx = base + c;
        if (idx < N_NODES) {
            g_row_start[idx] = run;
            run += g_cnt_in[idx];
        }
    }
    if (t == 0) g_row_start[N_NODES] = N_EDGES;
    for (int i = t; i < N_NODES; i += 1024) {
        g_rs_out[i] = rsqrtf((float)max(g_cnt_out[i], 1));
        g_rs_in [i] = rsqrtf((float)max(g_cnt_in [i], 1));
    }
}

// ---------------- atomic-free CSR scatter ----------------
__global__ void k_scatter() {
    int e = blockIdx.x * blockDim.x + threadIdx.x;
    if (e >= N_EDGES) return;
    int d = g_dst[e];
    g_csr[g_row_start[d] + g_rank[e]] = g_src[e];
}

// ---------------- GEMM1: T1 = (rs_out*X) @ W1   [10000x128 @ 128x128] ----------------
// block (32,8), tile 32 rows x 128 cols, 4 rows x 4 cols per thread, f32x2 FMA.
__global__ void k_gemm1(const float* __restrict__ X, const float* __restrict__ W1) {
    __shared__ float xs[32][F_IN];
    __shared__ float ws[16][F_H];
    const int tx = threadIdx.x;            // 0..31 -> col quad
    const int ty = threadIdx.y;            // 0..7  -> row group of 4
    const int tid = ty * 32 + tx;
    const int rb = blockIdx.x * 32;

    for (int f = tid; f < 32 * 32; f += 256) {   // 1024 float4 = 32x128
        int row = f >> 5, c4 = f & 31;
        int node = rb + row;
        float4 v = make_float4(0.f, 0.f, 0.f, 0.f);
        if (node < N_NODES) {
            v = ((const float4*)X)[node * 32 + c4];
            float r = g_rs_out[node];
            v.x *= r; v.y *= r; v.z *= r; v.w *= r;
        }
        ((float4*)xs[row])[c4] = v;
    }

    ull acc[4][2];
    #pragma unroll
    for (int q = 0; q < 4; q++) { acc[q][0] = 0ull; acc[q][1] = 0ull; }

    for (int kc = 0; kc < 8; kc++) {
        __syncthreads();
        for (int f = tid; f < 16 * 32; f += 256) {   // 512 float4 = 16x128
            int r = f >> 5, c4 = f & 31;
            ((float4*)ws[r])[c4] = ((const float4*)W1)[(kc * 16 + r) * 32 + c4];
        }
        __syncthreads();
        #pragma unroll
        for (int kk = 0; kk < 16; kk++) {
            float4 wv = ((float4*)ws[kk])[tx];
            ull w01 = pack2(wv.x, wv.y);
            ull w23 = pack2(wv.z, wv.w);
            #pragma unroll
            for (int q = 0; q < 4; q++) {
                float x = xs[ty * 4 + q][kc * 16 + kk];
                ull xx = pack2(x, x);
                acc[q][0] = fma2(xx, w01, acc[q][0]);
                acc[q][1] = fma2(xx, w23, acc[q][1]);
            }
        }
    }
    #pragma unroll
    for (int q = 0; q < 4; q++) {
        int node = rb + ty * 4 + q;
        if (node < N_NODES) {
            float4 o;
            unpack2(acc[q][0], o.x, o.y);
            unpack2(acc[q][1], o.z, o.w);
            ((float4*)g_T1)[node * 32 + tx] = o;
        }
    }
}

// ---------------- SpMM1 + epilogue: H = relu(rs_in*agg(T1)+b1)*rs_out ----------------
// warp per node, float4 rows, shuffle-broadcast edge indices.
__global__ void k_spmm1(const float* __restrict__ b1) {
    const int w = threadIdx.x >> 5, lane = threadIdx.x & 31;
    const int i = blockIdx.x * 4 + w;               // grid 2500 -> exactly 10000
    const int s = g_row_start[i], e = g_row_start[i + 1];
    const float4* __restrict__ T = (const float4*)g_T1;
    float4 a0 = make_float4(0,0,0,0), a1 = a0, a2 = a0, a3 = a0;
    for (int base = s; base < e; base += 32) {
        int n = min(32, e - base);
        int idx = (base + lane < e) ? g_csr[base + lane] : 0;
        int t = 0;
        for (; t + 4 <= n; t += 4) {
            int i0 = __shfl_sync(0xffffffffu, idx, t + 0);
            int i1 = __shfl_sync(0xffffffffu, idx, t + 1);
            int i2 = __shfl_sync(0xffffffffu, idx, t + 2);
            int i3 = __shfl_sync(0xffffffffu, idx, t + 3);
            float4 v0 = T[i0 * 32 + lane];
            float4 v1 = T[i1 * 32 + lane];
            float4 v2 = T[i2 * 32 + lane];
            float4 v3 = T[i3 * 32 + lane];
            a0.x += v0.x; a0.y += v0.y; a0.z += v0.z; a0.w += v0.w;
            a1.x += v1.x; a1.y += v1.y; a1.z += v1.z; a1.w += v1.w;
            a2.x += v2.x; a2.y += v2.y; a2.z += v2.z; a2.w += v2.w;
            a3.x += v3.x; a3.y += v3.y; a3.z += v3.z; a3.w += v3.w;
        }
        for (; t < n; t++) {
            int i0 = __shfl_sync(0xffffffffu, idx, t);
            float4 v0 = T[i0 * 32 + lane];
            a0.x += v0.x; a0.y += v0.y; a0.z += v0.z; a0.w += v0.w;
        }
    }
    float4 acc;
    acc.x = (a0.x + a1.x) + (a2.x + a3.x);
    acc.y = (a0.y + a1.y) + (a2.y + a3.y);
    acc.z = (a0.z + a1.z) + (a2.z + a3.z);
    acc.w = (a0.w + a1.w) + (a2.w + a3.w);
    float ri = g_rs_in[i], ro = g_rs_out[i];
    float4 bb = ((const float4*)b1)[lane];
    float4 h;
    h.x = fmaxf(fmaf(acc.x, ri, bb.x), 0.f) * ro;
    h.y = fmaxf(fmaf(acc.y, ri, bb.y), 0.f) * ro;
    h.z = fmaxf(fmaf(acc.z, ri, bb.z), 0.f) * ro;
    h.w = fmaxf(fmaf(acc.w, ri, bb.w), 0.f) * ro;
    ((float4*)g_H)[i * 32 + lane] = h;
}

// ---------------- GEMM2: T2 = H @ W2   [10000x128 @ 128x64] ----------------
// block (16,16), tile 64 rows x 64 cols, 4 rows x 4 cols per thread.
__global__ void k_gemm2(const float* __restrict__ W2) {
    __shared__ float xs[64][F_H];
    __shared__ float ws[16][F_OUT];
    const int tx = threadIdx.x;            // 0..15 -> col quad
    const int ty = threadIdx.y;            // 0..15 -> row group of 4
    const int tid = ty * 16 + tx;
    const int rb = blockIdx.x * 64;

    for (int f = tid; f < 64 * 32; f += 256) {   // 2048 float4 = 64x128
        int row = f >> 5, c4 = f & 31;
        int node = rb + row;
        float4 v = make_float4(0.f, 0.f, 0.f, 0.f);
        if (node < N_NODES) v = ((const float4*)g_H)[node * 32 + c4];
        ((float4*)xs[row])[c4] = v;
    }

    ull acc[4][2];
    #pragma unroll
    for (int q = 0; q < 4; q++) { acc[q][0] = 0ull; acc[q][1] = 0ull; }

    for (int kc = 0; kc < 8; kc++) {
        __syncthreads();
        for (int f = tid; f < 16 * 16; f += 256) {   // 256 float4 = 16x64
            int r = f >> 4, c4 = f & 15;
            ((float4*)ws[r])[c4] = ((const float4*)W2)[(kc * 16 + r) * 16 + c4];
        }
        __syncthreads();
        #pragma unroll
        for (int kk = 0; kk < 16; kk++) {
            float4 wv = ((float4*)ws[kk])[tx];
            ull w01 = pack2(wv.x, wv.y);
            ull w23 = pack2(wv.z, wv.w);
            #pragma unroll
            for (int q = 0; q < 4; q++) {
                float x = xs[ty * 4 + q][kc * 16 + kk];
                ull xx = pack2(x, x);
                acc[q][0] = fma2(xx, w01, acc[q][0]);
                acc[q][1] = fma2(xx, w23, acc[q][1]);
            }
        }
    }
    #pragma unroll
    for (int q = 0; q < 4; q++) {
        int node = rb + ty * 4 + q;
        if (node < N_NODES) {
            float4 o;
            unpack2(acc[q][0], o.x, o.y);
            unpack2(acc[q][1], o.z, o.w);
            ((float4*)g_T2)[node * 16 + tx] = o;
        }
    }
}

// ---------------- SpMM2 + epilogue into d_out ----------------
// warp per node, float2 rows (64 floats), shuffle-broadcast edges.
__global__ void k_spmm2(const float* __restrict__ b2, float* __restrict__ out) {
    const int w = threadIdx.x >> 5, lane = threadIdx.x & 31;
    const int i = blockIdx.x * 4 + w;               // grid 2500 -> exactly 10000
    const int s = g_row_start[i], e = g_row_start[i + 1];
    const float2* __restrict__ T = (const float2*)g_T2;
    float2 a0 = make_float2(0,0), a1 = a0, a2 = a0, a3 = a0;
    for (int base = s; base < e; base += 32) {
        int n = min(32, e - base);
        int idx = (base + lane < e) ? g_csr[base + lane] : 0;
        int t = 0;
        for (; t + 4 <= n; t += 4) {
            int i0 = __shfl_sync(0xffffffffu, idx, t + 0);
            int i1 = __shfl_sync(0xffffffffu, idx, t + 1);
            int i2 = __shfl_sync(0xffffffffu, idx, t + 2);
            int i3 = __shfl_sync(0xffffffffu, idx, t + 3);
            float2 v0 = T[i0 * 32 + lane];
            float2 v1 = T[i1 * 32 + lane];
            float2 v2 = T[i2 * 32 + lane];
            float2 v3 = T[i3 * 32 + lane];
            a0.x += v0.x; a0.y += v0.y;
            a1.x += v1.x; a1.y += v1.y;
            a2.x += v2.x; a2.y += v2.y;
            a3.x += v3.x; a3.y += v3.y;
        }
        for (; t < n; t++) {
            int i0 = __shfl_sync(0xffffffffu, idx, t);
            float2 v0 = T[i0 * 32 + lane];
            a0.x += v0.x; a0.y += v0.y;
        }
    }
    float2 acc;
    acc.x = (a0.x + a1.x) + (a2.x + a3.x);
    acc.y = (a0.y + a1.y) + (a2.y + a3.y);
    float ri = g_rs_in[i];
    float2 bb = ((const float2*)b2)[lane];
    float2 o;
    o.x = fmaf(acc.x, ri, bb.x);
    o.y = fmaf(acc.y, ri, bb.y);
    ((float2*)out)[i * 32 + lane] = o;
}

// ---------------- launch ----------------
extern "C" void kernel_launch(void* const* d_in, const int* in_sizes, int n_in,
                              void* d_out, int out_size) {
    const float* in_feat = (const float*)d_in[0];
    const void*  src     = d_in[1];
    const void*  dst     = d_in[2];
    const float* W1      = (const float*)d_in[3];
    const float* b1      = (const float*)d_in[4];
    const float* W2      = (const float*)d_in[5];
    const float* b2      = (const float*)d_in[6];
    float* out = (float*)d_out;

    const int EB = (N_EDGES + 255) / 256;
    const int NB = (N_NODES + 255) / 256;

    k_detect<<<1, 32>>>((const unsigned int*)src);
    k_zero<<<NB, 256>>>();
    k_prep<<<EB, 256>>>(src, dst);
    k_scan<<<1, 1024>>>();
    k_scatter<<<EB, 256>>>();
    k_gemm1<<<(N_NODES + 31) / 32, dim3(32, 8)>>>(in_feat, W1);
    k_spmm1<<<N_NODES / 4, 128>>>(b1);
    k_gemm2<<<(N_NODES + 63) / 64, dim3(16, 16)>>>(W2);
    k_spmm2<<<N_NODES / 4, 128>>>(b2, out);
}

// round 7
// speedup vs baseline: 1.3164x; 1.0839x over previous
#include <cuda_runtime.h>
#include <cuda_bf16.h>

#define N_NODES 10000
#define N_EDGES 640000
#define F_IN    128
#define F_H     128
#define F_OUT   64
#define NBLK    40          // ceil(10000/256)

typedef unsigned long long ull;

// ---------------- scratch (device globals; no allocation allowed) ----------------
__device__ int   g_is64;
__device__ int   g_src[N_EDGES];
__device__ int   g_dst[N_EDGES];
__device__ int   g_rank[N_EDGES];
__device__ int   g_cnt_out[N_NODES];
__device__ int   g_cnt_in[N_NODES];
__device__ float g_rs_out[N_NODES];
__device__ float g_rs_in[N_NODES];
__device__ int   g_row_start[N_NODES + 1];
__device__ int   g_partial[NBLK];
__device__ int   g_csr[N_EDGES];          // src indices grouped by dst
__device__ float g_T1[N_NODES * F_H];     // (rs_out * X) @ W1
__device__ float g_H [N_NODES * F_H];     // relu(...) * rs_out (pre-scaled for layer2)
__device__ float g_T2[N_NODES * F_OUT];   // H @ W2

// ---------------- packed f32x2 FMA helpers ----------------
__device__ __forceinline__ ull fma2(ull a, ull b, ull c) {
    ull d;
    asm("fma.rn.f32x2 %0, %1, %2, %3;" : "=l"(d) : "l"(a), "l"(b), "l"(c));
    return d;
}
__device__ __forceinline__ ull pack2(float lo, float hi) {
    ull d;
    asm("mov.b64 %0, {%1, %2};" : "=l"(d) : "f"(lo), "f"(hi));
    return d;
}
__device__ __forceinline__ void unpack2(ull v, float& lo, float& hi) {
    asm("mov.b64 {%0, %1}, %2;" : "=f"(lo), "=f"(hi) : "l"(v));
}

// ---------------- init: zero counts + dtype detection (merged) ----------------
__global__ void k_init(const unsigned int* __restrict__ raw) {
    int i = blockIdx.x * blockDim.x + threadIdx.x;
    if (i < N_NODES) { g_cnt_out[i] = 0; g_cnt_in[i] = 0; }
    if (i == 0) {
        int is64 = 1;
        for (int k = 0; k < 64; k++)
            if (raw[2 * k + 1] != 0u) is64 = 0;
        g_is64 = is64;
    }
}

// ---------------- fused convert + degree + rank capture ----------------
__global__ void k_prep(const void* __restrict__ sraw, const void* __restrict__ draw) {
    int e = blockIdx.x * blockDim.x + threadIdx.x;
    if (e >= N_EDGES) return;
    int s, d;
    if (g_is64) {
        s = (int)((const long long*)sraw)[e];
        d = (int)((const long long*)draw)[e];
    } else {
        s = ((const int*)sraw)[e];
        d = ((const int*)draw)[e];
    }
    g_src[e] = s;
    g_dst[e] = d;
    atomicAdd(&g_cnt_out[s], 1);                 // RED (no return)
    g_rank[e] = atomicAdd(&g_cnt_in[d], 1);      // rank within CSR row
}

// ---------------- scan stage A: per-block degree sums (40 blocks) ----------------
__global__ void k_scanA() {
    const int t = threadIdx.x, b = blockIdx.x;
    int i = b * 256 + t;
    int c = (i < N_NODES) ? g_cnt_in[i] : 0;
    #pragma unroll
    for (int d = 16; d > 0; d >>= 1) c += __shfl_down_sync(0xffffffffu, c, d);
    __shared__ int ws[8];
    if ((t & 31) == 0) ws[t >> 5] = c;
    __syncthreads();
    if (t < 8) {
        int s = ws[t];
        #pragma unroll
        for (int d = 4; d > 0; d >>= 1) s += __shfl_down_sync(0xffu, s, d);
        if (t == 0) g_partial[b] = s;
    }
}

// ---------------- scan stage C: offsets + block scan + rsqrt (40 blocks) ----------------
__global__ void k_scanC() {
    __shared__ int sp[64];
    __shared__ int warp_sums[8];
    __shared__ int s_off;
    const int t = threadIdx.x, b = blockIdx.x;

    if (t < 64) sp[t] = (t < NBLK) ? g_partial[t] : 0;
    __syncthreads();
    #pragma unroll
    for (int off = 1; off < 64; off <<= 1) {
        int v = (t < 64 && t >= off) ? sp[t - off] : 0;
        __syncthreads();
        if (t < 64) sp[t] += v;
        __syncthreads();
    }
    if (t == 0) s_off = (b > 0) ? sp[b - 1] : 0;

    const int i = b * 256 + t;
    const int c = (i < N_NODES) ? g_cnt_in[i] : 0;
    const int lane = t & 31, w = t >> 5;
    int v = c;
    #pragma unroll
    for (int d = 1; d < 32; d <<= 1) {
        int u = __shfl_up_sync(0xffffffffu, v, d);
        if (lane >= d) v += u;
    }
    if (lane == 31) warp_sums[w] = v;
    __syncthreads();                      // also publishes s_off
    if (w == 0) {
        int s = (lane < 8) ? warp_sums[lane] : 0;
        #pragma unroll
        for (int d = 1; d < 8; d <<= 1) {
            int u = __shfl_up_sync(0xffffffffu, s, d);
            if (lane >= d) s += u;
        }
        if (lane < 8) warp_sums[lane] = s;
    }
    __syncthreads();
    int excl = v - c + ((w > 0) ? warp_sums[w - 1] : 0);
    if (i < N_NODES) {
        g_row_start[i] = s_off + excl;
        g_rs_in [i] = rsqrtf((float)max(c, 1));
        g_rs_out[i] = rsqrtf((float)max(g_cnt_out[i], 1));
    }
    if (i == 0) g_row_start[N_NODES] = N_EDGES;
}

// ---------------- atomic-free CSR scatter ----------------
__global__ void k_scatter() {
    int e = blockIdx.x * blockDim.x + threadIdx.x;
    if (e >= N_EDGES) return;
    int d = g_dst[e];
    g_csr[g_row_start[d] + g_rank[e]] = g_src[e];
}

// ---------------- GEMM1: T1 = (rs_out*X) @ W1   [10000x128 @ 128x128] ----------------
__global__ void k_gemm1(const float* __restrict__ X, const float* __restrict__ W1) {
    __shared__ float xs[32][F_IN];
    __shared__ float ws[16][F_H];
    const int tx = threadIdx.x;            // 0..31 -> col quad
    const int ty = threadIdx.y;            // 0..7  -> row group of 4
    const int tid = ty * 32 + tx;
    const int rb = blockIdx.x * 32;

    for (int f = tid; f < 32 * 32; f += 256) {
        int row = f >> 5, c4 = f & 31;
        int node = rb + row;
        float4 v = make_float4(0.f, 0.f, 0.f, 0.f);
        if (node < N_NODES) {
            v = ((const float4*)X)[node * 32 + c4];
            float r = g_rs_out[node];
            v.x *= r; v.y *= r; v.z *= r; v.w *= r;
        }
        ((float4*)xs[row])[c4] = v;
    }

    ull acc[4][2];
    #pragma unroll
    for (int q = 0; q < 4; q++) { acc[q][0] = 0ull; acc[q][1] = 0ull; }

    for (int kc = 0; kc < 8; kc++) {
        __syncthreads();
        for (int f = tid; f < 16 * 32; f += 256) {
            int r = f >> 5, c4 = f & 31;
            ((float4*)ws[r])[c4] = ((const float4*)W1)[(kc * 16 + r) * 32 + c4];
        }
        __syncthreads();
        #pragma unroll
        for (int kk = 0; kk < 16; kk++) {
            float4 wv = ((float4*)ws[kk])[tx];
            ull w01 = pack2(wv.x, wv.y);
            ull w23 = pack2(wv.z, wv.w);
            #pragma unroll
            for (int q = 0; q < 4; q++) {
                float x = xs[ty * 4 + q][kc * 16 + kk];
                ull xx = pack2(x, x);
                acc[q][0] = fma2(xx, w01, acc[q][0]);
                acc[q][1] = fma2(xx, w23, acc[q][1]);
            }
        }
    }
    #pragma unroll
    for (int q = 0; q < 4; q++) {
        int node = rb + ty * 4 + q;
        if (node < N_NODES) {
            float4 o;
            unpack2(acc[q][0], o.x, o.y);
            unpack2(acc[q][1], o.z, o.w);
            ((float4*)g_T1)[node * 32 + tx] = o;
        }
    }
}

// ---------------- SpMM1 + epilogue: H = relu(rs_in*agg(T1)+b1)*rs_out ----------------
__global__ void k_spmm1(const float* __restrict__ b1) {
    const int w = threadIdx.x >> 5, lane = threadIdx.x & 31;
    const int i = blockIdx.x * 4 + w;
    const int s = g_row_start[i], e = g_row_start[i + 1];
    const float4* __restrict__ T = (const float4*)g_T1;
    float4 a0 = make_float4(0,0,0,0), a1 = a0, a2 = a0, a3 = a0;
    for (int base = s; base < e; base += 32) {
        int n = min(32, e - base);
        int idx = (base + lane < e) ? g_csr[base + lane] : 0;
        int t = 0;
        for (; t + 4 <= n; t += 4) {
            int i0 = __shfl_sync(0xffffffffu, idx, t + 0);
            int i1 = __shfl_sync(0xffffffffu, idx, t + 1);
            int i2 = __shfl_sync(0xffffffffu, idx, t + 2);
            int i3 = __shfl_sync(0xffffffffu, idx, t + 3);
            float4 v0 = T[i0 * 32 + lane];
            float4 v1 = T[i1 * 32 + lane];
            float4 v2 = T[i2 * 32 + lane];
            float4 v3 = T[i3 * 32 + lane];
            a0.x += v0.x; a0.y += v0.y; a0.z += v0.z; a0.w += v0.w;
            a1.x += v1.x; a1.y += v1.y; a1.z += v1.z; a1.w += v1.w;
            a2.x += v2.x; a2.y += v2.y; a2.z += v2.z; a2.w += v2.w;
            a3.x += v3.x; a3.y += v3.y; a3.z += v3.z; a3.w += v3.w;
        }
        for (; t < n; t++) {
            int i0 = __shfl_sync(0xffffffffu, idx, t);
            float4 v0 = T[i0 * 32 + lane];
            a0.x += v0.x; a0.y += v0.y; a0.z += v0.z; a0.w += v0.w;
        }
    }
    float4 acc;
    acc.x = (a0.x + a1.x) + (a2.x + a3.x);
    acc.y = (a0.y + a1.y) + (a2.y + a3.y);
    acc.z = (a0.z + a1.z) + (a2.z + a3.z);
    acc.w = (a0.w + a1.w) + (a2.w + a3.w);
    float ri = g_rs_in[i], ro = g_rs_out[i];
    float4 bb = ((const float4*)b1)[lane];
    float4 h;
    h.x = fmaxf(fmaf(acc.x, ri, bb.x), 0.f) * ro;
    h.y = fmaxf(fmaf(acc.y, ri, bb.y), 0.f) * ro;
    h.z = fmaxf(fmaf(acc.z, ri, bb.z), 0.f) * ro;
    h.w = fmaxf(fmaf(acc.w, ri, bb.w), 0.f) * ro;
    ((float4*)g_H)[i * 32 + lane] = h;
}

// ---------------- GEMM2: T2 = H @ W2   [10000x128 @ 128x64] ----------------
__global__ void k_gemm2(const float* __restrict__ W2) {
    __shared__ float xs[64][F_H];
    __shared__ float ws[16][F_OUT];
    const int tx = threadIdx.x;            // 0..15
    const int ty = threadIdx.y;            // 0..15
    const int tid = ty * 16 + tx;
    const int rb = blockIdx.x * 64;

    for (int f = tid; f < 64 * 32; f += 256) {
        int row = f >> 5, c4 = f & 31;
        int node = rb + row;
        float4 v = make_float4(0.f, 0.f, 0.f, 0.f);
        if (node < N_NODES) v = ((const float4*)g_H)[node * 32 + c4];
        ((float4*)xs[row])[c4] = v;
    }

    ull acc[4][2];
    #pragma unroll
    for (int q = 0; q < 4; q++) { acc[q][0] = 0ull; acc[q][1] = 0ull; }

    for (int kc = 0; kc < 8; kc++) {
        __syncthreads();
        for (int f = tid; f < 16 * 16; f += 256) {
            int r = f >> 4, c4 = f & 15;
            ((float4*)ws[r])[c4] = ((const float4*)W2)[(kc * 16 + r) * 16 + c4];
        }
        __syncthreads();
        #pragma unroll
        for (int kk = 0; kk < 16; kk++) {
            float4 wv = ((float4*)ws[kk])[tx];
            ull w01 = pack2(wv.x, wv.y);
            ull w23 = pack2(wv.z, wv.w);
            #pragma unroll
            for (int q = 0; q < 4; q++) {
                float x = xs[ty * 4 + q][kc * 16 + kk];
                ull xx = pack2(x, x);
                acc[q][0] = fma2(xx, w01, acc[q][0]);
                acc[q][1] = fma2(xx, w23, acc[q][1]);
            }
        }
    }
    #pragma unroll
    for (int q = 0; q < 4; q++) {
        int node = rb + ty * 4 + q;
        if (node < N_NODES) {
            float4 o;
            unpack2(acc[q][0], o.x, o.y);
            unpack2(acc[q][1], o.z, o.w);
            ((float4*)g_T2)[node * 16 + tx] = o;
        }
    }
}

// ---------------- SpMM2 + epilogue into d_out ----------------
__global__ void k_spmm2(const float* __restrict__ b2, float* __restrict__ out) {
    const int w = threadIdx.x >> 5, lane = threadIdx.x & 31;
    const int i = blockIdx.x * 4 + w;
    const int s = g_row_start[i], e = g_row_start[i + 1];
    const float2* __restrict__ T = (const float2*)g_T2;
    float2 a0 = make_float2(0,0), a1 = a0, a2 = a0, a3 = a0;
    for (int base = s; base < e; base += 32) {
        int n = min(32, e - base);
        int idx = (base + lane < e) ? g_csr[base + lane] : 0;
        int t = 0;
        for (; t + 4 <= n; t += 4) {
            int i0 = __shfl_sync(0xffffffffu, idx, t + 0);
            int i1 = __shfl_sync(0xffffffffu, idx, t + 1);
            int i2 = __shfl_sync(0xffffffffu, idx, t + 2);
            int i3 = __shfl_sync(0xffffffffu, idx, t + 3);
            float2 v0 = T[i0 * 32 + lane];
            float2 v1 = T[i1 * 32 + lane];
            float2 v2 = T[i2 * 32 + lane];
            float2 v3 = T[i3 * 32 + lane];
            a0.x += v0.x; a0.y += v0.y;
            a1.x += v1.x; a1.y += v1.y;
            a2.x += v2.x; a2.y += v2.y;
            a3.x += v3.x; a3.y += v3.y;
        }
        for (; t < n; t++) {
            int i0 = __shfl_sync(0xffffffffu, idx, t);
            float2 v0 = T[i0 * 32 + lane];
            a0.x += v0.x; a0.y += v0.y;
        }
    }
    float2 acc;
    acc.x = (a0.x + a1.x) + (a2.x + a3.x);
    acc.y = (a0.y + a1.y) + (a2.y + a3.y);
    float ri = g_rs_in[i];
    float2 bb = ((const float2*)b2)[lane];
    float2 o;
    o.x = fmaf(acc.x, ri, bb.x);
    o.y = fmaf(acc.y, ri, bb.y);
    ((float2*)out)[i * 32 + lane] = o;
}

// ---------------- launch ----------------
extern "C" void kernel_launch(void* const* d_in, const int* in_sizes, int n_in,
                              void* d_out, int out_size) {
    const float* in_feat = (const float*)d_in[0];
    const void*  src     = d_in[1];
    const void*  dst     = d_in[2];
    const float* W1      = (const float*)d_in[3];
    const float* b1      = (const float*)d_in[4];
    const float* W2      = (const float*)d_in[5];
    const float* b2      = (const float*)d_in[6];
    float* out = (float*)d_out;

    const int EB = (N_EDGES + 255) / 256;

    k_init<<<NBLK, 256>>>((const unsigned int*)src);
    k_prep<<<EB, 256>>>(src, dst);
    k_scanA<<<NBLK, 256>>>();
    k_scanC<<<NBLK, 256>>>();
    k_scatter<<<EB, 256>>>();
    k_gemm1<<<(N_NODES + 31) / 32, dim3(32, 8)>>>(in_feat, W1);
    k_spmm1<<<N_NODES / 4, 128>>>(b1);
    k_gemm2<<<(N_NODES + 63) / 64, dim3(16, 16)>>>(W2);
    k_spmm2<<<N_NODES / 4, 128>>>(b2, out);
}

// round 8
// speedup vs baseline: 1.3228x; 1.0049x over previous
#include <cuda_runtime.h>
#include <cuda_bf16.h>
#include <cuda_fp16.h>

#define N_NODES 10000
#define N_EDGES 640000
#define F_IN    128
#define F_H     128
#define F_OUT   64
#define NBLK    40          // ceil(10000/256)

typedef unsigned long long ull;

// ---------------- scratch (device globals; no allocation allowed) ----------------
__device__ int    g_is64;
__device__ int    g_src[N_EDGES];
__device__ int    g_dst[N_EDGES];
__device__ int    g_rank[N_EDGES];
__device__ int    g_cnt_out[N_NODES];
__device__ int    g_cnt_in[N_NODES];
__device__ float  g_rs_out[N_NODES];
__device__ float  g_rs_in[N_NODES];
__device__ int    g_row_start[N_NODES + 1];
__device__ int    g_partial[NBLK];
__device__ int    g_csr[N_EDGES];           // src indices grouped by dst
__device__ __half g_T1h[N_NODES * F_H];     // fp16: (rs_out * X) @ W1
__device__ float  g_H [N_NODES * F_H];      // relu(...) * rs_out (fp32)
__device__ __half g_T2h[N_NODES * F_OUT];   // fp16: H @ W2

// ---------------- packed f32x2 FMA helpers ----------------
__device__ __forceinline__ ull fma2(ull a, ull b, ull c) {
    ull d;
    asm("fma.rn.f32x2 %0, %1, %2, %3;" : "=l"(d) : "l"(a), "l"(b), "l"(c));
    return d;
}
__device__ __forceinline__ ull pack2(float lo, float hi) {
    ull d;
    asm("mov.b64 %0, {%1, %2};" : "=l"(d) : "f"(lo), "f"(hi));
    return d;
}
__device__ __forceinline__ void unpack2(ull v, float& lo, float& hi) {
    asm("mov.b64 {%0, %1}, %2;" : "=f"(lo), "=f"(hi) : "l"(v));
}

// ---------------- init: zero counts + dtype detection (merged) ----------------
__global__ void k_init(const unsigned int* __restrict__ raw) {
    int i = blockIdx.x * blockDim.x + threadIdx.x;
    if (i < N_NODES) { g_cnt_out[i] = 0; g_cnt_in[i] = 0; }
    if (i == 0) {
        int is64 = 1;
        for (int k = 0; k < 64; k++)
            if (raw[2 * k + 1] != 0u) is64 = 0;
        g_is64 = is64;
    }
}

// ---------------- fused convert + degree + rank capture ----------------
__global__ void k_prep(const void* __restrict__ sraw, const void* __restrict__ draw) {
    int e = blockIdx.x * blockDim.x + threadIdx.x;
    if (e >= N_EDGES) return;
    int s, d;
    if (g_is64) {
        s = (int)((const long long*)sraw)[e];
        d = (int)((const long long*)draw)[e];
    } else {
        s = ((const int*)sraw)[e];
        d = ((const int*)draw)[e];
    }
    g_src[e] = s;
    g_dst[e] = d;
    atomicAdd(&g_cnt_out[s], 1);                 // RED (no return)
    g_rank[e] = atomicAdd(&g_cnt_in[d], 1);      // rank within CSR row
}

// ---------------- scan stage A: per-block degree sums (40 blocks) ----------------
__global__ void k_scanA() {
    const int t = threadIdx.x, b = blockIdx.x;
    int i = b * 256 + t;
    int c = (i < N_NODES) ? g_cnt_in[i] : 0;
    #pragma unroll
    for (int d = 16; d > 0; d >>= 1) c += __shfl_down_sync(0xffffffffu, c, d);
    __shared__ int ws[8];
    if ((t & 31) == 0) ws[t >> 5] = c;
    __syncthreads();
    if (t < 8) {
        int s = ws[t];
        #pragma unroll
        for (int d = 4; d > 0; d >>= 1) s += __shfl_down_sync(0xffu, s, d);
        if (t == 0) g_partial[b] = s;
    }
}

// ---------------- scan stage C: offsets + block scan + rsqrt (40 blocks) ----------------
__global__ void k_scanC() {
    __shared__ int sp[64];
    __shared__ int warp_sums[8];
    __shared__ int s_off;
    const int t = threadIdx.x, b = blockIdx.x;

    if (t < 64) sp[t] = (t < NBLK) ? g_partial[t] : 0;
    __syncthreads();
    #pragma unroll
    for (int off = 1; off < 64; off <<= 1) {
        int v = (t < 64 && t >= off) ? sp[t - off] : 0;
        __syncthreads();
        if (t < 64) sp[t] += v;
        __syncthreads();
    }
    if (t == 0) s_off = (b > 0) ? sp[b - 1] : 0;

    const int i = b * 256 + t;
    const int c = (i < N_NODES) ? g_cnt_in[i] : 0;
    const int lane = t & 31, w = t >> 5;
    int v = c;
    #pragma unroll
    for (int d = 1; d < 32; d <<= 1) {
        int u = __shfl_up_sync(0xffffffffu, v, d);
        if (lane >= d) v += u;
    }
    if (lane == 31) warp_sums[w] = v;
    __syncthreads();
    if (w == 0) {
        int s = (lane < 8) ? warp_sums[lane] : 0;
        #pragma unroll
        for (int d = 1; d < 8; d <<= 1) {
            int u = __shfl_up_sync(0xffffffffu, s, d);
            if (lane >= d) s += u;
        }
        if (lane < 8) warp_sums[lane] = s;
    }
    __syncthreads();
    int excl = v - c + ((w > 0) ? warp_sums[w - 1] : 0);
    if (i < N_NODES) {
        g_row_start[i] = s_off + excl;
        g_rs_in [i] = rsqrtf((float)max(c, 1));
        g_rs_out[i] = rsqrtf((float)max(g_cnt_out[i], 1));
    }
    if (i == 0) g_row_start[N_NODES] = N_EDGES;
}

// ---------------- atomic-free CSR scatter ----------------
__global__ void k_scatter() {
    int e = blockIdx.x * blockDim.x + threadIdx.x;
    if (e >= N_EDGES) return;
    int d = g_dst[e];
    g_csr[g_row_start[d] + g_rank[e]] = g_src[e];
}

// ---------------- GEMM1: T1h = fp16( (rs_out*X) @ W1 )  [10000x128 @ 128x128] ----------------
__global__ void k_gemm1(const float* __restrict__ X, const float* __restrict__ W1) {
    __shared__ float xs[32][F_IN];
    __shared__ float ws[16][F_H];
    const int tx = threadIdx.x;            // 0..31 -> col quad
    const int ty = threadIdx.y;            // 0..7  -> row group of 4
    const int tid = ty * 32 + tx;
    const int rb = blockIdx.x * 32;

    for (int f = tid; f < 32 * 32; f += 256) {
        int row = f >> 5, c4 = f & 31;
        int node = rb + row;
        float4 v = make_float4(0.f, 0.f, 0.f, 0.f);
        if (node < N_NODES) {
            v = ((const float4*)X)[node * 32 + c4];
            float r = g_rs_out[node];
            v.x *= r; v.y *= r; v.z *= r; v.w *= r;
        }
        ((float4*)xs[row])[c4] = v;
    }

    ull acc[4][2];
    #pragma unroll
    for (int q = 0; q < 4; q++) { acc[q][0] = 0ull; acc[q][1] = 0ull; }

    for (int kc = 0; kc < 8; kc++) {
        __syncthreads();
        for (int f = tid; f < 16 * 32; f += 256) {
            int r = f >> 5, c4 = f & 31;
            ((float4*)ws[r])[c4] = ((const float4*)W1)[(kc * 16 + r) * 32 + c4];
        }
        __syncthreads();
        #pragma unroll
        for (int kk = 0; kk < 16; kk++) {
            float4 wv = ((float4*)ws[kk])[tx];
            ull w01 = pack2(wv.x, wv.y);
            ull w23 = pack2(wv.z, wv.w);
            #pragma unroll
            for (int q = 0; q < 4; q++) {
                float x = xs[ty * 4 + q][kc * 16 + kk];
                ull xx = pack2(x, x);
                acc[q][0] = fma2(xx, w01, acc[q][0]);
                acc[q][1] = fma2(xx, w23, acc[q][1]);
            }
        }
    }
    #pragma unroll
    for (int q = 0; q < 4; q++) {
        int node = rb + ty * 4 + q;
        if (node < N_NODES) {
            float4 o;
            unpack2(acc[q][0], o.x, o.y);
            unpack2(acc[q][1], o.z, o.w);
            __half2 h0 = __float22half2_rn(make_float2(o.x, o.y));
            __half2 h1 = __float22half2_rn(make_float2(o.z, o.w));
            uint2 u;
            u.x = *(unsigned int*)&h0;
            u.y = *(unsigned int*)&h1;
            ((uint2*)g_T1h)[node * 32 + tx] = u;   // row = 128 halves = 32 uint2
        }
    }
}

// ---------------- SpMM1 + epilogue: H = relu(rs_in*agg(T1h)+b1)*rs_out ----------------
// warp per node; lane loads one uint2 (4 halves, LDG.64); fp32 accumulate.
__global__ void k_spmm1(const float* __restrict__ b1) {
    const int w = threadIdx.x >> 5, lane = threadIdx.x & 31;
    const int i = blockIdx.x * 4 + w;
    const int s = g_row_start[i], e = g_row_start[i + 1];
    const uint2* __restrict__ T = (const uint2*)g_T1h;
    float4 a0 = make_float4(0,0,0,0), a1 = a0, a2 = a0, a3 = a0;
    for (int base = s; base < e; base += 32) {
        int n = min(32, e - base);
        int idx = (base + lane < e) ? g_csr[base + lane] : 0;
        int t = 0;
        for (; t + 4 <= n; t += 4) {
            int i0 = __shfl_sync(0xffffffffu, idx, t + 0);
            int i1 = __shfl_sync(0xffffffffu, idx, t + 1);
            int i2 = __shfl_sync(0xffffffffu, idx, t + 2);
            int i3 = __shfl_sync(0xffffffffu, idx, t + 3);
            uint2 u0 = T[i0 * 32 + lane];
            uint2 u1 = T[i1 * 32 + lane];
            uint2 u2 = T[i2 * 32 + lane];
            uint2 u3 = T[i3 * 32 + lane];
            float2 f;
            f = __half22float2(*(__half2*)&u0.x); a0.x += f.x; a0.y += f.y;
            f = __half22float2(*(__half2*)&u0.y); a0.z += f.x; a0.w += f.y;
            f = __half22float2(*(__half2*)&u1.x); a1.x += f.x; a1.y += f.y;
            f = __half22float2(*(__half2*)&u1.y); a1.z += f.x; a1.w += f.y;
            f = __half22float2(*(__half2*)&u2.x); a2.x += f.x; a2.y += f.y;
            f = __half22float2(*(__half2*)&u2.y); a2.z += f.x; a2.w += f.y;
            f = __half22float2(*(__half2*)&u3.x); a3.x += f.x; a3.y += f.y;
            f = __half22float2(*(__half2*)&u3.y); a3.z += f.x; a3.w += f.y;
        }
        for (; t < n; t++) {
            int i0 = __shfl_sync(0xffffffffu, idx, t);
            uint2 u0 = T[i0 * 32 + lane];
            float2 f;
            f = __half22float2(*(__half2*)&u0.x); a0.x += f.x; a0.y += f.y;
            f = __half22float2(*(__half2*)&u0.y); a0.z += f.x; a0.w += f.y;
        }
    }
    float4 acc;
    acc.x = (a0.x + a1.x) + (a2.x + a3.x);
    acc.y = (a0.y + a1.y) + (a2.y + a3.y);
    acc.z = (a0.z + a1.z) + (a2.z + a3.z);
    acc.w = (a0.w + a1.w) + (a2.w + a3.w);
    float ri = g_rs_in[i], ro = g_rs_out[i];
    float4 bb = ((const float4*)b1)[lane];
    float4 h;
    h.x = fmaxf(fmaf(acc.x, ri, bb.x), 0.f) * ro;
    h.y = fmaxf(fmaf(acc.y, ri, bb.y), 0.f) * ro;
    h.z = fmaxf(fmaf(acc.z, ri, bb.z), 0.f) * ro;
    h.w = fmaxf(fmaf(acc.w, ri, bb.w), 0.f) * ro;
    ((float4*)g_H)[i * 32 + lane] = h;
}

// ---------------- GEMM2: T2h = fp16( H @ W2 )   [10000x128 @ 128x64] ----------------
__global__ void k_gemm2(const float* __restrict__ W2) {
    __shared__ float xs[64][F_H];
    __shared__ float ws[16][F_OUT];
    const int tx = threadIdx.x;            // 0..15
    const int ty = threadIdx.y;            // 0..15
    const int tid = ty * 16 + tx;
    const int rb = blockIdx.x * 64;

    for (int f = tid; f < 64 * 32; f += 256) {
        int row = f >> 5, c4 = f & 31;
        int node = rb + row;
        float4 v = make_float4(0.f, 0.f, 0.f, 0.f);
        if (node < N_NODES) v = ((const float4*)g_H)[node * 32 + c4];
        ((float4*)xs[row])[c4] = v;
    }

    ull acc[4][2];
    #pragma unroll
    for (int q = 0; q < 4; q++) { acc[q][0] = 0ull; acc[q][1] = 0ull; }

    for (int kc = 0; kc < 8; kc++) {
        __syncthreads();
        for (int f = tid; f < 16 * 16; f += 256) {
            int r = f >> 4, c4 = f & 15;
            ((float4*)ws[r])[c4] = ((const float4*)W2)[(kc * 16 + r) * 16 + c4];
        }
        __syncthreads();
        #pragma unroll
        for (int kk = 0; kk < 16; kk++) {
            float4 wv = ((float4*)ws[kk])[tx];
            ull w01 = pack2(wv.x, wv.y);
            ull w23 = pack2(wv.z, wv.w);
            #pragma unroll
            for (int q = 0; q < 4; q++) {
                float x = xs[ty * 4 + q][kc * 16 + kk];
                ull xx = pack2(x, x);
                acc[q][0] = fma2(xx, w01, acc[q][0]);
                acc[q][1] = fma2(xx, w23, acc[q][1]);
            }
        }
    }
    #pragma unroll
    for (int q = 0; q < 4; q++) {
        int node = rb + ty * 4 + q;
        if (node < N_NODES) {
            float4 o;
            unpack2(acc[q][0], o.x, o.y);
            unpack2(acc[q][1], o.z, o.w);
            __half2 h0 = __float22half2_rn(make_float2(o.x, o.y));
            __half2 h1 = __float22half2_rn(make_float2(o.z, o.w));
            uint2 u;
            u.x = *(unsigned int*)&h0;
            u.y = *(unsigned int*)&h1;
            ((uint2*)g_T2h)[node * 16 + tx] = u;   // row = 64 halves = 16 uint2
        }
    }
}

// ---------------- SpMM2 + epilogue into d_out ----------------
// warp per node; lane loads one half2 (LDG.32); fp32 accumulate.
__global__ void k_spmm2(const float* __restrict__ b2, float* __restrict__ out) {
    const int w = threadIdx.x >> 5, lane = threadIdx.x & 31;
    const int i = blockIdx.x * 4 + w;
    const int s = g_row_start[i], e = g_row_start[i + 1];
    const unsigned int* __restrict__ T = (const unsigned int*)g_T2h;
    float2 a0 = make_float2(0,0), a1 = a0, a2 = a0, a3 = a0;
    for (int base = s; base < e; base += 32) {
        int n = min(32, e - base);
        int idx = (base + lane < e) ? g_csr[base + lane] : 0;
        int t = 0;
        for (; t + 4 <= n; t += 4) {
            int i0 = __shfl_sync(0xffffffffu, idx, t + 0);
            int i1 = __shfl_sync(0xffffffffu, idx, t + 1);
            int i2 = __shfl_sync(0xffffffffu, idx, t + 2);
            int i3 = __shfl_sync(0xffffffffu, idx, t + 3);
            unsigned int u0 = T[i0 * 32 + lane];
            unsigned int u1 = T[i1 * 32 + lane];
            unsigned int u2 = T[i2 * 32 + lane];
            unsigned int u3 = T[i3 * 32 + lane];
            float2 f;
            f = __half22float2(*(__half2*)&u0); a0.x += f.x; a0.y += f.y;
            f = __half22float2(*(__half2*)&u1); a1.x += f.x; a1.y += f.y;
            f = __half22float2(*(__half2*)&u2); a2.x += f.x; a2.y += f.y;
            f = __half22float2(*(__half2*)&u3); a3.x += f.x; a3.y += f.y;
        }
        for (; t < n; t++) {
            int i0 = __shfl_sync(0xffffffffu, idx, t);
            unsigned int u0 = T[i0 * 32 + lane];
            float2 f = __half22float2(*(__half2*)&u0);
            a0.x += f.x; a0.y += f.y;
        }
    }
    float2 acc;
    acc.x = (a0.x + a1.x) + (a2.x + a3.x);
    acc.y = (a0.y + a1.y) + (a2.y + a3.y);
    float ri = g_rs_in[i];
    float2 bb = ((const float2*)b2)[lane];
    float2 o;
    o.x = fmaf(acc.x, ri, bb.x);
    o.y = fmaf(acc.y, ri, bb.y);
    ((float2*)out)[i * 32 + lane] = o;
}

// ---------------- launch ----------------
extern "C" void kernel_launch(void* const* d_in, const int* in_sizes, int n_in,
                              void* d_out, int out_size) {
    const float* in_feat = (const float*)d_in[0];
    const void*  src     = d_in[1];
    const void*  dst     = d_in[2];
    const float* W1      = (const float*)d_in[3];
    const float* b1      = (const float*)d_in[4];
    const float* W2      = (const float*)d_in[5];
    const float* b2      = (const float*)d_in[6];
    float* out = (float*)d_out;

    const int EB = (N_EDGES + 255) / 256;

    k_init<<<NBLK, 256>>>((const unsigned int*)src);
    k_prep<<<EB, 256>>>(src, dst);
    k_scanA<<<NBLK, 256>>>();
    k_scanC<<<NBLK, 256>>>();
    k_scatter<<<EB, 256>>>();
    k_gemm1<<<(N_NODES + 31) / 32, dim3(32, 8)>>>(in_feat, W1);
    k_spmm1<<<N_NODES / 4, 128>>>(b1);
    k_gemm2<<<(N_NODES + 63) / 64, dim3(16, 16)>>>(W2);
    k_spmm2<<<N_NODES / 4, 128>>>(b2, out);
}